// round 1
// baseline (speedup 1.0000x reference)
#include <cuda_runtime.h>
#include <math.h>

#define NEP 256
#define NS  32
#define DIN 512
#define DF  512
#define T   1026
#define TT  513
#define R2  8      // z-rows per block in logvar kernel
#define CH  64     // t-chunk in pairwise kernel

// LOG(2*pi*e)
#define LOG_2PIE 2.8378770664093453f

// -------- device scratch (no allocations allowed) --------
__device__ float g_mu [2][NEP][T];   // z (mu)
__device__ float g_elv[2][NEP][T];   // exp(lv)
__device__ float g_eml[2][NEP][T];   // exp(-lv)
__device__ float g_H  [2][NEP];
__device__ float g_score[NEP][NEP];

// ============================================================
// K1: per-(episode,set): phi = relu(in @ W_fe + b), then
// z = [mean_n(x), std_n(x,ddof=1)] for x=[targets, phi]
// grid (NEP, 2), block 512, dynamic smem = 32*512*4 + 32*4
// ============================================================
__global__ void k_stats(const float* __restrict__ trin, const float* __restrict__ trtg,
                        const float* __restrict__ tein, const float* __restrict__ tetg,
                        const float* __restrict__ Wfe,  const float* __restrict__ bfe)
{
    extern __shared__ float s_dyn[];
    const int e   = blockIdx.x;
    const int set = blockIdx.y;
    const float* in = (set ? tein : trin) + (size_t)e * NS * DIN;
    const float* tg = (set ? tetg : trtg) + (size_t)e * NS;

    float4* sIn = (float4*)s_dyn;            // [32][128] float4
    float*  sTg = s_dyn + NS * DIN;          // 32 floats
    const int tid = threadIdx.x;             // 512 threads

    const float4* gin = (const float4*)in;
    for (int k = tid; k < NS * DIN / 4; k += 512) sIn[k] = gin[k];
    if (tid < NS) sTg[tid] = tg[tid];
    __syncthreads();

    const int f = tid;                       // output feature
    float acc[NS];
    {
        float b = bfe[f];
        #pragma unroll
        for (int n = 0; n < NS; n++) acc[n] = b;
    }

    for (int d4 = 0; d4 < DIN / 4; d4++) {
        const int d = d4 * 4;
        float w0 = Wfe[(size_t)(d + 0) * DF + f];
        float w1 = Wfe[(size_t)(d + 1) * DF + f];
        float w2 = Wfe[(size_t)(d + 2) * DF + f];
        float w3 = Wfe[(size_t)(d + 3) * DF + f];
        #pragma unroll
        for (int n = 0; n < NS; n++) {
            float4 v = sIn[n * (DIN / 4) + d4];
            acc[n] = fmaf(v.x, w0, acc[n]);
            acc[n] = fmaf(v.y, w1, acc[n]);
            acc[n] = fmaf(v.z, w2, acc[n]);
            acc[n] = fmaf(v.w, w3, acc[n]);
        }
    }

    // relu + two-pass mean/std (ddof=1)
    float s = 0.f;
    #pragma unroll
    for (int n = 0; n < NS; n++) { acc[n] = fmaxf(acc[n], 0.f); s += acc[n]; }
    const float mean = s * (1.f / NS);
    float ss = 0.f;
    #pragma unroll
    for (int n = 0; n < NS; n++) { float d_ = acc[n] - mean; ss = fmaf(d_, d_, ss); }
    const float stdv = sqrtf(ss * (1.f / (NS - 1)));

    g_mu[set][e][1 + f]      = mean;
    g_mu[set][e][TT + 1 + f] = stdv;

    if (f == 0) {  // targets column (feature 0 of x)
        float st = 0.f;
        #pragma unroll
        for (int n = 0; n < NS; n++) st += sTg[n];
        float m = st * (1.f / NS);
        float q = 0.f;
        #pragma unroll
        for (int n = 0; n < NS; n++) { float d_ = sTg[n] - m; q = fmaf(d_, d_, q); }
        g_mu[set][e][0]  = m;
        g_mu[set][e][TT] = sqrtf(q * (1.f / (NS - 1)));
    }
}

// ============================================================
// K2: logvar = clip(z @ W_lv + b_lv, -9, -2) for R2 rows/block,
// produce exp(lv), exp(-lv), H = sum(lv) + 0.5*T*log(2*pi*e)
// grid (NEP/R2, 2), block 256
// ============================================================
__global__ void k_logvar(const float* __restrict__ Wlv, const float* __restrict__ blv)
{
    const int set = blockIdx.y;
    const int r0  = blockIdx.x * R2;
    __shared__ float sz[R2][1028];           // padded for float4
    __shared__ float sH[R2];
    const int tid = threadIdx.x;

    for (int idx = tid; idx < R2 * 1028; idx += 256) {
        int r = idx / 1028, k = idx % 1028;
        sz[r][k] = (k < T) ? g_mu[set][r0 + r][k] : 0.f;
    }
    if (tid < R2) sH[tid] = 0.f;
    __syncthreads();

    float hpart[R2];
    #pragma unroll
    for (int r = 0; r < R2; r++) hpart[r] = 0.f;

    for (int t = tid; t < T; t += 256) {
        float acc[R2];
        {
            float b = blv[t];
            #pragma unroll
            for (int r = 0; r < R2; r++) acc[r] = b;
        }
        for (int k4 = 0; k4 < 256; k4++) {
            const int k = k4 * 4;
            float w0 = Wlv[(size_t)(k + 0) * T + t];
            float w1 = Wlv[(size_t)(k + 1) * T + t];
            float w2 = Wlv[(size_t)(k + 2) * T + t];
            float w3 = Wlv[(size_t)(k + 3) * T + t];
            #pragma unroll
            for (int r = 0; r < R2; r++) {
                float4 v = ((const float4*)&sz[r][0])[k4];
                acc[r] = fmaf(v.x, w0, acc[r]);
                acc[r] = fmaf(v.y, w1, acc[r]);
                acc[r] = fmaf(v.z, w2, acc[r]);
                acc[r] = fmaf(v.w, w3, acc[r]);
            }
        }
        // tail k = 1024, 1025
        #pragma unroll
        for (int k = 1024; k < T; k++) {
            float w = Wlv[(size_t)k * T + t];
            #pragma unroll
            for (int r = 0; r < R2; r++) acc[r] = fmaf(sz[r][k], w, acc[r]);
        }
        #pragma unroll
        for (int r = 0; r < R2; r++) {
            float lv = fminf(fmaxf(acc[r], -9.f), -2.f);
            hpart[r] += lv;
            g_elv[set][r0 + r][t] = expf(lv);
            g_eml[set][r0 + r][t] = expf(-lv);
        }
    }
    #pragma unroll
    for (int r = 0; r < R2; r++) atomicAdd(&sH[r], hpart[r]);
    __syncthreads();
    if (tid < R2) g_H[set][r0 + tid] = sH[tid] + 0.5f * (float)T * LOG_2PIE;
}

// ============================================================
// K3: pairwise score. (l2-l1) terms cancel between directions:
// score[i,j] = 0.5*sum_t[(e1+d^2)*q2 + (e2+d^2)*q1] - T + H1[i] + H2[j]
// grid (16,16), block 256, 16x16 score tile per block
// ============================================================
__global__ void k_pair()
{
    __shared__ float sm1[16][CH + 1], se1[16][CH + 1], sq1[16][CH + 1];
    __shared__ float sm2[16][CH + 1], se2[16][CH + 1], sq2[16][CH + 1];
    const int tid = threadIdx.x;
    const int ty = tid >> 4, tx = tid & 15;
    const int i = blockIdx.y * 16 + ty;
    const int j = blockIdx.x * 16 + tx;

    float acc = 0.f;
    for (int c0 = 0; c0 < T; c0 += CH) {
        __syncthreads();
        for (int u = tid; u < 16 * CH; u += 256) {
            int rr = u / CH, t = u % CH;
            int tg = c0 + t;
            bool ok = tg < T;
            int ii = blockIdx.y * 16 + rr;
            int jj = blockIdx.x * 16 + rr;
            sm1[rr][t] = ok ? g_mu [0][ii][tg] : 0.f;
            se1[rr][t] = ok ? g_elv[0][ii][tg] : 0.f;
            sq1[rr][t] = ok ? g_eml[0][ii][tg] : 0.f;  // q=0 pad kills both terms
            sm2[rr][t] = ok ? g_mu [1][jj][tg] : 0.f;
            se2[rr][t] = ok ? g_elv[1][jj][tg] : 0.f;
            sq2[rr][t] = ok ? g_eml[1][jj][tg] : 0.f;
        }
        __syncthreads();
        #pragma unroll 8
        for (int t = 0; t < CH; t++) {
            float m1 = sm1[ty][t], e1 = se1[ty][t], q1 = sq1[ty][t];
            float m2 = sm2[tx][t], e2 = se2[tx][t], q2 = sq2[tx][t];
            float d = m1 - m2;
            float dd = d * d;
            acc = fmaf(e1 + dd, q2, acc);
            acc = fmaf(e2 + dd, q1, acc);
        }
    }
    g_score[i][j] = 0.5f * acc - (float)T + g_H[0][i] + g_H[1][j];
}

// ============================================================
// K4: probs = log_softmax(-score, axis=1); one block per row
// ============================================================
__global__ void k_softmax(float* __restrict__ out)
{
    const int i = blockIdx.x;
    const int j = threadIdx.x;   // 256
    __shared__ float red[256];
    float v = -g_score[i][j];
    red[j] = v;
    __syncthreads();
    for (int s = 128; s > 0; s >>= 1) {
        if (j < s) red[j] = fmaxf(red[j], red[j + s]);
        __syncthreads();
    }
    float mx = red[0];
    __syncthreads();
    float ex = expf(v - mx);
    red[j] = ex;
    __syncthreads();
    for (int s = 128; s > 0; s >>= 1) {
        if (j < s) red[j] += red[j + s];
        __syncthreads();
    }
    float lse = mx + logf(red[0]);
    out[(size_t)i * NEP + j] = v - lse;
}

// classes tail: arange(NEP) as the output dtype (float32)
__global__ void k_classes(float* __restrict__ out, int n)
{
    int k = blockIdx.x * blockDim.x + threadIdx.x;
    if (k < n) out[NEP * NEP + k] = (float)k;
}

// ============================================================
extern "C" void kernel_launch(void* const* d_in, const int* in_sizes, int n_in,
                              void* d_out, int out_size)
{
    const float* train_inputs  = (const float*)d_in[0];
    const float* train_targets = (const float*)d_in[1];
    const float* test_inputs   = (const float*)d_in[2];
    const float* test_targets  = (const float*)d_in[3];
    const float* W_fe          = (const float*)d_in[4];
    const float* b_fe          = (const float*)d_in[5];
    const float* W_lv          = (const float*)d_in[6];
    const float* b_lv          = (const float*)d_in[7];
    float* out = (float*)d_out;

    const int smem_stats = NS * DIN * sizeof(float) + NS * sizeof(float); // 65664
    cudaFuncSetAttribute(k_stats, cudaFuncAttributeMaxDynamicSharedMemorySize, smem_stats);

    k_stats<<<dim3(NEP, 2), 512, smem_stats>>>(train_inputs, train_targets,
                                               test_inputs, test_targets, W_fe, b_fe);
    k_logvar<<<dim3(NEP / R2, 2), 256>>>(W_lv, b_lv);
    k_pair<<<dim3(16, 16), 256>>>();
    k_softmax<<<NEP, 256>>>(out);

    int rem = out_size - NEP * NEP;
    if (rem > 0) {
        k_classes<<<(rem + 255) / 256, 256>>>(out, rem);
    }
}

// round 2
// speedup vs baseline: 1.0010x; 1.0010x over previous
#include <cuda_runtime.h>
#include <math.h>

#define NEP 256
#define NS  32
#define DIN 512
#define DF  512
#define T   1026
#define TT  513
#define R2  8      // z-rows per block in logvar kernel
#define CH  64     // t-chunk in pairwise kernel

// LOG(2*pi*e)
#define LOG_2PIE 2.8378770664093453f

// -------- device scratch (no allocations allowed) --------
__device__ float g_mu [2][NEP][T];   // z (mu)
__device__ float g_elv[2][NEP][T];   // exp(lv)
__device__ float g_eml[2][NEP][T];   // exp(-lv)
__device__ float g_H  [2][NEP];
__device__ float g_score[NEP][NEP];

// ============================================================
// K1: per-(episode,set): phi = relu(in @ W_fe + b), then
// z = [mean_n(x), std_n(x,ddof=1)] for x=[targets, phi]
// grid (NEP, 2), block 512, dynamic smem = 32*512*4 + 32*4
// ============================================================
__global__ void k_stats(const float* __restrict__ trin, const float* __restrict__ trtg,
                        const float* __restrict__ tein, const float* __restrict__ tetg,
                        const float* __restrict__ Wfe,  const float* __restrict__ bfe)
{
    extern __shared__ float s_dyn[];
    const int e   = blockIdx.x;
    const int set = blockIdx.y;
    const float* in = (set ? tein : trin) + (size_t)e * NS * DIN;
    const float* tg = (set ? tetg : trtg) + (size_t)e * NS;

    float4* sIn = (float4*)s_dyn;            // [32][128] float4
    float*  sTg = s_dyn + NS * DIN;          // 32 floats
    const int tid = threadIdx.x;             // 512 threads

    const float4* gin = (const float4*)in;
    for (int k = tid; k < NS * DIN / 4; k += 512) sIn[k] = gin[k];
    if (tid < NS) sTg[tid] = tg[tid];
    __syncthreads();

    const int f = tid;                       // output feature
    float acc[NS];
    {
        float b = bfe[f];
        #pragma unroll
        for (int n = 0; n < NS; n++) acc[n] = b;
    }

    for (int d4 = 0; d4 < DIN / 4; d4++) {
        const int d = d4 * 4;
        float w0 = Wfe[(size_t)(d + 0) * DF + f];
        float w1 = Wfe[(size_t)(d + 1) * DF + f];
        float w2 = Wfe[(size_t)(d + 2) * DF + f];
        float w3 = Wfe[(size_t)(d + 3) * DF + f];
        #pragma unroll
        for (int n = 0; n < NS; n++) {
            float4 v = sIn[n * (DIN / 4) + d4];
            acc[n] = fmaf(v.x, w0, acc[n]);
            acc[n] = fmaf(v.y, w1, acc[n]);
            acc[n] = fmaf(v.z, w2, acc[n]);
            acc[n] = fmaf(v.w, w3, acc[n]);
        }
    }

    // relu + two-pass mean/std (ddof=1)
    float s = 0.f;
    #pragma unroll
    for (int n = 0; n < NS; n++) { acc[n] = fmaxf(acc[n], 0.f); s += acc[n]; }
    const float mean = s * (1.f / NS);
    float ss = 0.f;
    #pragma unroll
    for (int n = 0; n < NS; n++) { float d_ = acc[n] - mean; ss = fmaf(d_, d_, ss); }
    const float stdv = sqrtf(ss * (1.f / (NS - 1)));

    g_mu[set][e][1 + f]      = mean;
    g_mu[set][e][TT + 1 + f] = stdv;

    if (f == 0) {  // targets column (feature 0 of x)
        float st = 0.f;
        #pragma unroll
        for (int n = 0; n < NS; n++) st += sTg[n];
        float m = st * (1.f / NS);
        float q = 0.f;
        #pragma unroll
        for (int n = 0; n < NS; n++) { float d_ = sTg[n] - m; q = fmaf(d_, d_, q); }
        g_mu[set][e][0]  = m;
        g_mu[set][e][TT] = sqrtf(q * (1.f / (NS - 1)));
    }
}

// ============================================================
// K2: logvar = clip(z @ W_lv + b_lv, -9, -2) for R2 rows/block,
// produce exp(lv), exp(-lv), H = sum(lv) + 0.5*T*log(2*pi*e)
// grid (NEP/R2, 2), block 256
// ============================================================
__global__ void k_logvar(const float* __restrict__ Wlv, const float* __restrict__ blv)
{
    const int set = blockIdx.y;
    const int r0  = blockIdx.x * R2;
    __shared__ float sz[R2][1028];           // padded for float4
    __shared__ float sH[R2];
    const int tid = threadIdx.x;

    for (int idx = tid; idx < R2 * 1028; idx += 256) {
        int r = idx / 1028, k = idx % 1028;
        sz[r][k] = (k < T) ? g_mu[set][r0 + r][k] : 0.f;
    }
    if (tid < R2) sH[tid] = 0.f;
    __syncthreads();

    float hpart[R2];
    #pragma unroll
    for (int r = 0; r < R2; r++) hpart[r] = 0.f;

    for (int t = tid; t < T; t += 256) {
        float acc[R2];
        {
            float b = blv[t];
            #pragma unroll
            for (int r = 0; r < R2; r++) acc[r] = b;
        }
        for (int k4 = 0; k4 < 256; k4++) {
            const int k = k4 * 4;
            float w0 = Wlv[(size_t)(k + 0) * T + t];
            float w1 = Wlv[(size_t)(k + 1) * T + t];
            float w2 = Wlv[(size_t)(k + 2) * T + t];
            float w3 = Wlv[(size_t)(k + 3) * T + t];
            #pragma unroll
            for (int r = 0; r < R2; r++) {
                float4 v = ((const float4*)&sz[r][0])[k4];
                acc[r] = fmaf(v.x, w0, acc[r]);
                acc[r] = fmaf(v.y, w1, acc[r]);
                acc[r] = fmaf(v.z, w2, acc[r]);
                acc[r] = fmaf(v.w, w3, acc[r]);
            }
        }
        // tail k = 1024, 1025
        #pragma unroll
        for (int k = 1024; k < T; k++) {
            float w = Wlv[(size_t)k * T + t];
            #pragma unroll
            for (int r = 0; r < R2; r++) acc[r] = fmaf(sz[r][k], w, acc[r]);
        }
        #pragma unroll
        for (int r = 0; r < R2; r++) {
            float lv = fminf(fmaxf(acc[r], -9.f), -2.f);
            hpart[r] += lv;
            g_elv[set][r0 + r][t] = expf(lv);
            g_eml[set][r0 + r][t] = expf(-lv);
        }
    }
    #pragma unroll
    for (int r = 0; r < R2; r++) atomicAdd(&sH[r], hpart[r]);
    __syncthreads();
    if (tid < R2) g_H[set][r0 + tid] = sH[tid] + 0.5f * (float)T * LOG_2PIE;
}

// ============================================================
// K3: pairwise score. (l2-l1) terms cancel between directions:
// score[i,j] = 0.5*sum_t[(e1+d^2)*q2 + (e2+d^2)*q1] - T + H1[i] + H2[j]
// grid (16,16), block 256, 16x16 score tile per block
// ============================================================
__global__ void k_pair()
{
    __shared__ float sm1[16][CH + 1], se1[16][CH + 1], sq1[16][CH + 1];
    __shared__ float sm2[16][CH + 1], se2[16][CH + 1], sq2[16][CH + 1];
    const int tid = threadIdx.x;
    const int ty = tid >> 4, tx = tid & 15;
    const int i = blockIdx.y * 16 + ty;
    const int j = blockIdx.x * 16 + tx;

    float acc = 0.f;
    for (int c0 = 0; c0 < T; c0 += CH) {
        __syncthreads();
        for (int u = tid; u < 16 * CH; u += 256) {
            int rr = u / CH, t = u % CH;
            int tg = c0 + t;
            bool ok = tg < T;
            int ii = blockIdx.y * 16 + rr;
            int jj = blockIdx.x * 16 + rr;
            sm1[rr][t] = ok ? g_mu [0][ii][tg] : 0.f;
            se1[rr][t] = ok ? g_elv[0][ii][tg] : 0.f;
            sq1[rr][t] = ok ? g_eml[0][ii][tg] : 0.f;  // q=0 pad kills both terms
            sm2[rr][t] = ok ? g_mu [1][jj][tg] : 0.f;
            se2[rr][t] = ok ? g_elv[1][jj][tg] : 0.f;
            sq2[rr][t] = ok ? g_eml[1][jj][tg] : 0.f;
        }
        __syncthreads();
        #pragma unroll 8
        for (int t = 0; t < CH; t++) {
            float m1 = sm1[ty][t], e1 = se1[ty][t], q1 = sq1[ty][t];
            float m2 = sm2[tx][t], e2 = se2[tx][t], q2 = sq2[tx][t];
            float d = m1 - m2;
            float dd = d * d;
            acc = fmaf(e1 + dd, q2, acc);
            acc = fmaf(e2 + dd, q1, acc);
        }
    }
    g_score[i][j] = 0.5f * acc - (float)T + g_H[0][i] + g_H[1][j];
}

// ============================================================
// K4: probs = log_softmax(-score, axis=1); one block per row
// ============================================================
__global__ void k_softmax(float* __restrict__ out)
{
    const int i = blockIdx.x;
    const int j = threadIdx.x;   // 256
    __shared__ float red[256];
    float v = -g_score[i][j];
    red[j] = v;
    __syncthreads();
    for (int s = 128; s > 0; s >>= 1) {
        if (j < s) red[j] = fmaxf(red[j], red[j + s]);
        __syncthreads();
    }
    float mx = red[0];
    __syncthreads();
    float ex = expf(v - mx);
    red[j] = ex;
    __syncthreads();
    for (int s = 128; s > 0; s >>= 1) {
        if (j < s) red[j] += red[j + s];
        __syncthreads();
    }
    float lse = mx + logf(red[0]);
    out[(size_t)i * NEP + j] = v - lse;
}

// classes tail: arange(NEP) as the output dtype (float32)
__global__ void k_classes(float* __restrict__ out, int n)
{
    int k = blockIdx.x * blockDim.x + threadIdx.x;
    if (k < n) out[NEP * NEP + k] = (float)k;
}

// ============================================================
extern "C" void kernel_launch(void* const* d_in, const int* in_sizes, int n_in,
                              void* d_out, int out_size)
{
    const float* train_inputs  = (const float*)d_in[0];
    const float* train_targets = (const float*)d_in[1];
    const float* test_inputs   = (const float*)d_in[2];
    const float* test_targets  = (const float*)d_in[3];
    const float* W_fe          = (const float*)d_in[4];
    const float* b_fe          = (const float*)d_in[5];
    const float* W_lv          = (const float*)d_in[6];
    const float* b_lv          = (const float*)d_in[7];
    float* out = (float*)d_out;

    const int smem_stats = NS * DIN * sizeof(float) + NS * sizeof(float); // 65664
    cudaFuncSetAttribute(k_stats, cudaFuncAttributeMaxDynamicSharedMemorySize, smem_stats);

    k_stats<<<dim3(NEP, 2), 512, smem_stats>>>(train_inputs, train_targets,
                                               test_inputs, test_targets, W_fe, b_fe);
    k_logvar<<<dim3(NEP / R2, 2), 256>>>(W_lv, b_lv);
    k_pair<<<dim3(16, 16), 256>>>();
    k_softmax<<<NEP, 256>>>(out);

    int rem = out_size - NEP * NEP;
    if (rem > 0) {
        k_classes<<<(rem + 255) / 256, 256>>>(out, rem);
    }
}